// round 2
// baseline (speedup 1.0000x reference)
#include <cuda_runtime.h>
#include <cuda_bf16.h>
#include <cstdint>

// Problem constants (fixed by dataset)
#define HH   128
#define WW   128
#define NMAX 16384
#define NSPLIT 32
#define FXc 128.0f
#define FYc 128.0f
#define CXc 64.0f
#define CYc 64.0f
#define EPSc 1e-8f

// ---------------- static device scratch (no allocation allowed) -------------
__device__ float  d_Ex[(size_t)NMAX * 128];   // [g][x], opacity folded in
__device__ float  d_EyT[(size_t)128 * NMAX];  // [y][g]
__device__ float4 d_Col[NMAX];                // packed colors
__device__ float4 d_Part[NSPLIT][HH * WW];    // per-split partial {r,g,b,den}

// ---------------- f32x2 packed helpers (Blackwell FFMA2 path) ---------------
__device__ __forceinline__ unsigned long long f2pack(float a, float b) {
    unsigned long long r;
    asm("mov.b64 %0, {%1, %2};" : "=l"(r) : "f"(a), "f"(b));
    return r;
}
__device__ __forceinline__ void f2unpack(unsigned long long v, float& a, float& b) {
    asm("mov.b64 {%0, %1}, %2;" : "=f"(a), "=f"(b) : "l"(v));
}
__device__ __forceinline__ unsigned long long f2mul(unsigned long long a, unsigned long long b) {
    unsigned long long r;
    asm("mul.rn.f32x2 %0, %1, %2;" : "=l"(r) : "l"(a), "l"(b));
    return r;
}
__device__ __forceinline__ unsigned long long f2fma(unsigned long long a, unsigned long long b,
                                                    unsigned long long c) {
    unsigned long long r;
    asm("fma.rn.f32x2 %0, %1, %2, %3;" : "=l"(r) : "l"(a), "l"(b), "l"(c));
    return r;
}
__device__ __forceinline__ unsigned long long f2add(unsigned long long a, unsigned long long b) {
    unsigned long long r;
    asm("add.rn.f32x2 %0, %1, %2;" : "=l"(r) : "l"(a), "l"(b));
    return r;
}

// ---------------- precompute: projection + separable exp tables -------------
// grid = N blocks, 128 threads. Thread i of block g fills Ex[g][i] and EyT[i][g].
__global__ void __launch_bounds__(128) prep_kernel(
    const float* __restrict__ pos, const float* __restrict__ col,
    const float* __restrict__ opa, const float* __restrict__ sca,
    const float* __restrict__ qv,  const float* __restrict__ tv, int N)
{
    int g = blockIdx.x;
    int i = threadIdx.x;
    if (g >= N) return;

    float qw = qv[0], qx = qv[1], qy = qv[2], qz = qv[3];
    float qn = rsqrtf(qw * qw + qx * qx + qy * qy + qz * qz);
    qw *= qn; qx *= qn; qy *= qn; qz *= qn;

    float r00 = 1.f - 2.f * (qy * qy + qz * qz);
    float r01 = 2.f * (qx * qy - qz * qw);
    float r02 = 2.f * (qx * qz + qy * qw);
    float r10 = 2.f * (qx * qy + qz * qw);
    float r11 = 1.f - 2.f * (qx * qx + qz * qz);
    float r12 = 2.f * (qy * qz - qx * qw);
    float r20 = 2.f * (qx * qz - qy * qw);
    float r21 = 2.f * (qy * qz + qx * qw);
    float r22 = 1.f - 2.f * (qx * qx + qy * qy);

    float p0 = pos[3 * g + 0], p1 = pos[3 * g + 1], p2 = pos[3 * g + 2];
    float cx = r00 * p0 + r01 * p1 + r02 * p2 + tv[0];
    float cy = r10 * p0 + r11 * p1 + r12 * p2 + tv[1];
    float cz = r20 * p0 + r21 * p1 + r22 * p2 + tv[2];

    float invz = __fdividef(1.f, cz);
    float px = cx * invz * FXc + CXc;
    float py = cy * invz * FYc + CYc;

    float s = sca[g];
    float e = -0.5f * __fdividef(1.f, s * s);
    float o = opa[g];

    float dx = (float)i - px;
    d_Ex[(size_t)g * 128 + i] = o * __expf(e * dx * dx);
    float dy = (float)i - py;
    d_EyT[(size_t)i * NMAX + g] = __expf(e * dy * dy);

    if (i == 0)
        d_Col[g] = make_float4(col[3 * g + 0], col[3 * g + 1], col[3 * g + 2], 0.f);
}

// ---------------- main accumulation ----------------------------------------
// grid = (H/4, NSPLIT), 128 threads. Thread x handles 4 pixels: column x of
// rows y0..y0+3. Loops over this split's gaussian slice in chunks of 128,
// staging per-gaussian uniforms (ey of 4 rows + colors) into shared.
__global__ void __launch_bounds__(128) render_kernel(int N, int gPer)
{
    const int x    = threadIdx.x;
    const int y0   = blockIdx.x * 4;
    const int spl  = blockIdx.y;
    const int gBeg = spl * gPer;

    __shared__ unsigned long long sEy01[128], sEy23[128];
    __shared__ unsigned long long sCr[128], sCg[128], sCb[128];

    unsigned long long aR01 = 0ull, aR23 = 0ull;
    unsigned long long aG01 = 0ull, aG23 = 0ull;
    unsigned long long aB01 = 0ull, aB23 = 0ull;
    unsigned long long aD01 = 0ull, aD23 = 0ull;

    for (int c0 = 0; c0 < gPer; c0 += 128) {
        // ---- stage 128 gaussians' uniforms into shared ----
        {
            int g = gBeg + c0 + x;
            float ey0 = d_EyT[(size_t)(y0 + 0) * NMAX + g];
            float ey1 = d_EyT[(size_t)(y0 + 1) * NMAX + g];
            float ey2 = d_EyT[(size_t)(y0 + 2) * NMAX + g];
            float ey3 = d_EyT[(size_t)(y0 + 3) * NMAX + g];
            sEy01[x] = f2pack(ey0, ey1);
            sEy23[x] = f2pack(ey2, ey3);
            float4 c = d_Col[g];
            sCr[x] = f2pack(c.x, c.x);
            sCg[x] = f2pack(c.y, c.y);
            sCb[x] = f2pack(c.z, c.z);
        }
        __syncthreads();

        const float* exBase = &d_Ex[(size_t)(gBeg + c0) * 128 + x];
        #pragma unroll 8
        for (int j = 0; j < 128; ++j) {
            float ex = __ldg(exBase + j * 128);     // 128B/warp contiguous
            unsigned long long ex2 = f2pack(ex, ex);
            unsigned long long w01 = f2mul(ex2, sEy01[j]);
            unsigned long long w23 = f2mul(ex2, sEy23[j]);
            aR01 = f2fma(w01, sCr[j], aR01);
            aR23 = f2fma(w23, sCr[j], aR23);
            aG01 = f2fma(w01, sCg[j], aG01);
            aG23 = f2fma(w23, sCg[j], aG23);
            aB01 = f2fma(w01, sCb[j], aB01);
            aB23 = f2fma(w23, sCb[j], aB23);
            aD01 = f2add(aD01, w01);
            aD23 = f2add(aD23, w23);
        }
        __syncthreads();
    }

    float r0, r1, g0, g1, b0, b1, d0, d1;
    f2unpack(aR01, r0, r1); f2unpack(aG01, g0, g1);
    f2unpack(aB01, b0, b1); f2unpack(aD01, d0, d1);
    d_Part[spl][(y0 + 0) * WW + x] = make_float4(r0, g0, b0, d0);
    d_Part[spl][(y0 + 1) * WW + x] = make_float4(r1, g1, b1, d1);
    f2unpack(aR23, r0, r1); f2unpack(aG23, g0, g1);
    f2unpack(aB23, b0, b1); f2unpack(aD23, d0, d1);
    d_Part[spl][(y0 + 2) * WW + x] = make_float4(r0, g0, b0, d0);
    d_Part[spl][(y0 + 3) * WW + x] = make_float4(r1, g1, b1, d1);
}

// ---------------- finalize: reduce splits, divide, tile-scatter -------------
__global__ void __launch_bounds__(256) finalize_kernel(
    float* __restrict__ out, const int* __restrict__ tileHW,
    const int* __restrict__ chunkG, int N)
{
    int p = blockIdx.x * blockDim.x + threadIdx.x;
    if (p >= HH * WW) return;

    float r = 0.f, g = 0.f, b = 0.f, d = 0.f;
    #pragma unroll
    for (int s = 0; s < NSPLIT; ++s) {
        float4 v = d_Part[s][p];
        r += v.x; g += v.y; b += v.z; d += v.w;
    }

    int cg = chunkG[0];
    if (cg <= 0 || cg > N) cg = N;
    int nChunks = N / cg;
    d += (float)nChunks * EPSc;

    int tw = tileHW[0];
    if (tw <= 0 || tw > 128) tw = 64;
    int step = tw * tw;
    int t = p / step;
    int q = p - t * step;

    float inv = __fdividef(1.f, d);
    float* o = out + (size_t)t * 3 * step + q;
    o[0]        = r * inv;
    o[step]     = g * inv;
    o[2 * step] = b * inv;
}

// ---------------- launch ----------------------------------------------------
extern "C" void kernel_launch(void* const* d_in, const int* in_sizes, int n_in,
                              void* d_out, int out_size)
{
    const float* pos = (const float*)d_in[0];
    const float* col = (const float*)d_in[1];
    const float* opa = (const float*)d_in[2];
    const float* sca = (const float*)d_in[3];
    const float* qv  = (const float*)d_in[4];
    const float* tv  = (const float*)d_in[5];
    const int*   tHW = (n_in > 6) ? (const int*)d_in[6] : nullptr;
    const int*   cG  = (n_in > 7) ? (const int*)d_in[7] : nullptr;

    int N = in_sizes[0] / 3;
    if (N > NMAX) N = NMAX;

    prep_kernel<<<N, 128>>>(pos, col, opa, sca, qv, tv, N);

    int gPer = N / NSPLIT;
    render_kernel<<<dim3(HH / 4, NSPLIT), 128>>>(N, gPer);

    finalize_kernel<<<(HH * WW + 255) / 256, 256>>>((float*)d_out, tHW, cG, N);
}

// round 5
// speedup vs baseline: 1.7733x; 1.7733x over previous
#include <cuda_runtime.h>
#include <cuda_bf16.h>
#include <cstdint>

#define HH   128
#define WW   128
#define NMAX 16384
#define NSPLIT 32
#define KSLICE (NMAX / NSPLIT)       /* 512 */
#define KCHUNK 128
#define FXc 128.0f
#define FYc 128.0f
#define CXc 64.0f
#define CYc 64.0f
#define EPSc 1e-8f

// ---------------- static device scratch (no allocation allowed) -------------
// A = Ey [128 y][K g], B = weighted Ex [512 n][K], n = ch*128 + x,
// ch in {R,G,B,opacity}. Split-bf16 planes (hi/lo).
__device__ __nv_bfloat16 d_Ahi[(size_t)128 * NMAX];
__device__ __nv_bfloat16 d_Alo[(size_t)128 * NMAX];
__device__ __nv_bfloat16 d_Bhi[(size_t)512 * NMAX];
__device__ __nv_bfloat16 d_Blo[(size_t)512 * NMAX];
__device__ float         d_Part[NSPLIT][128][512];   // split-K partials (8 MB)

// ---------------- PTX helpers ------------------------------------------------
__device__ __forceinline__ uint32_t smem_u32(const void* p) {
    uint32_t a;
    asm("{ .reg .u64 t; cvta.to.shared.u64 t, %1; cvt.u32.u64 %0, t; }" : "=r"(a) : "l"(p));
    return a;
}
#define LDSM4(r0, r1, r2, r3, addr)                                          \
    asm volatile("ldmatrix.sync.aligned.m8n8.x4.shared.b16 {%0,%1,%2,%3}, [%4];" \
        : "=r"(r0), "=r"(r1), "=r"(r2), "=r"(r3) : "r"(addr))
#define MMA16816(d, a, b)                                                    \
    asm volatile("mma.sync.aligned.m16n8k16.row.col.f32.bf16.bf16.f32 "      \
        "{%0,%1,%2,%3}, {%4,%5,%6,%7}, {%8,%9}, {%0,%1,%2,%3};"              \
        : "+f"((d)[0]), "+f"((d)[1]), "+f"((d)[2]), "+f"((d)[3])             \
        : "r"((a)[0]), "r"((a)[1]), "r"((a)[2]), "r"((a)[3]),                \
          "r"((b)[0]), "r"((b)[1]))

// swizzled smem byte offset: row stride 256B (128 bf16), 16B-unit column c
__device__ __forceinline__ uint32_t swz(int r, int c) {
    return (uint32_t)(r * 256 + ((((c) & 8) | (((c) ^ (r)) & 7)) << 4));
}

__device__ __forceinline__ uint32_t pkbf(float a, float b) {
    __nv_bfloat162 h = __floats2bfloat162_rn(a, b);
    uint32_t u;
    memcpy(&u, &h, 4);
    return u;
}

// write 4 consecutive-g values to hi/lo planes with one STG.64 each
__device__ __forceinline__ void st4(__nv_bfloat16* __restrict__ hi,
                                    __nv_bfloat16* __restrict__ lo,
                                    size_t idx, float v0, float v1, float v2, float v3) {
    __nv_bfloat16 h0 = __float2bfloat16_rn(v0);
    __nv_bfloat16 h1 = __float2bfloat16_rn(v1);
    __nv_bfloat16 h2 = __float2bfloat16_rn(v2);
    __nv_bfloat16 h3 = __float2bfloat16_rn(v3);
    uint2 H;
    H.x = pkbf(__bfloat162float(h0), __bfloat162float(h1));
    H.y = pkbf(__bfloat162float(h2), __bfloat162float(h3));
    *reinterpret_cast<uint2*>(hi + idx) = H;
    uint2 L;
    L.x = pkbf(v0 - __bfloat162float(h0), v1 - __bfloat162float(h1));
    L.y = pkbf(v2 - __bfloat162float(h2), v3 - __bfloat162float(h3));
    *reinterpret_cast<uint2*>(lo + idx) = L;
}

// ---------------- prep: project + geometric-recurrence exp tables -----------
// 128 blocks x 32 threads; thread handles 4 consecutive gaussians.
__global__ void __launch_bounds__(32) prep_kernel(
    const float* __restrict__ pos, const float* __restrict__ col,
    const float* __restrict__ opa, const float* __restrict__ sca,
    const float* __restrict__ qv,  const float* __restrict__ tv)
{
    int g0 = (blockIdx.x * 32 + threadIdx.x) * 4;

    float qw = qv[0], qx = qv[1], qy = qv[2], qz = qv[3];
    float qn = rsqrtf(qw * qw + qx * qx + qy * qy + qz * qz);
    qw *= qn; qx *= qn; qy *= qn; qz *= qn;
    float r00 = 1.f - 2.f * (qy * qy + qz * qz), r01 = 2.f * (qx * qy - qz * qw), r02 = 2.f * (qx * qz + qy * qw);
    float r10 = 2.f * (qx * qy + qz * qw), r11 = 1.f - 2.f * (qx * qx + qz * qz), r12 = 2.f * (qy * qz - qx * qw);
    float r20 = 2.f * (qx * qz - qy * qw), r21 = 2.f * (qy * qz + qx * qw), r22 = 1.f - 2.f * (qx * qx + qy * qy);
    float t0 = tv[0], t1 = tv[1], t2 = tv[2];

    float px[4], py[4], ee[4], q2e[4], oo[4], ocr[4], ocg[4], ocb[4];
    #pragma unroll
    for (int j = 0; j < 4; ++j) {
        int g = g0 + j;
        float p0 = pos[3 * g + 0], p1 = pos[3 * g + 1], p2 = pos[3 * g + 2];
        float cx = r00 * p0 + r01 * p1 + r02 * p2 + t0;
        float cy = r10 * p0 + r11 * p1 + r12 * p2 + t1;
        float cz = r20 * p0 + r21 * p1 + r22 * p2 + t2;
        float invz = __fdividef(1.f, cz);
        px[j] = cx * invz * FXc + CXc;
        py[j] = cy * invz * FYc + CYc;
        float s = sca[g];
        ee[j] = -0.5f * __fdividef(1.f, s * s);
        q2e[j] = __expf(2.f * ee[j]);
        float o = opa[g];
        oo[j]  = o;
        ocr[j] = o * col[3 * g + 0];
        ocg[j] = o * col[3 * g + 1];
        ocb[j] = o * col[3 * g + 2];
    }

    // B rows: n = ch*128 + x, value = ex * weight_ch
    for (int xb = 0; xb < 128; xb += 16) {
        float tx[4], ux[4];
        #pragma unroll
        for (int j = 0; j < 4; ++j) {
            float dx = (float)xb - px[j];
            tx[j] = __expf(ee[j] * dx * dx);
            ux[j] = __expf(ee[j] * (2.f * dx + 1.f));
        }
        #pragma unroll
        for (int k = 0; k < 16; ++k) {
            int x = xb + k;
            st4(d_Bhi, d_Blo, (size_t)(0 * 128 + x) * NMAX + g0,
                tx[0] * ocr[0], tx[1] * ocr[1], tx[2] * ocr[2], tx[3] * ocr[3]);
            st4(d_Bhi, d_Blo, (size_t)(1 * 128 + x) * NMAX + g0,
                tx[0] * ocg[0], tx[1] * ocg[1], tx[2] * ocg[2], tx[3] * ocg[3]);
            st4(d_Bhi, d_Blo, (size_t)(2 * 128 + x) * NMAX + g0,
                tx[0] * ocb[0], tx[1] * ocb[1], tx[2] * ocb[2], tx[3] * ocb[3]);
            st4(d_Bhi, d_Blo, (size_t)(3 * 128 + x) * NMAX + g0,
                tx[0] * oo[0], tx[1] * oo[1], tx[2] * oo[2], tx[3] * oo[3]);
            #pragma unroll
            for (int j = 0; j < 4; ++j) { tx[j] *= ux[j]; ux[j] *= q2e[j]; }
        }
    }
    // A rows (Ey)
    for (int yb = 0; yb < 128; yb += 16) {
        float ty[4], uy[4];
        #pragma unroll
        for (int j = 0; j < 4; ++j) {
            float dy = (float)yb - py[j];
            ty[j] = __expf(ee[j] * dy * dy);
            uy[j] = __expf(ee[j] * (2.f * dy + 1.f));
        }
        #pragma unroll
        for (int k = 0; k < 16; ++k) {
            st4(d_Ahi, d_Alo, (size_t)(yb + k) * NMAX + g0, ty[0], ty[1], ty[2], ty[3]);
            #pragma unroll
            for (int j = 0; j < 4; ++j) { ty[j] *= uy[j]; uy[j] *= q2e[j]; }
        }
    }
}

// ---------------- GEMM via HMMA (mma.sync m16n8k16 bf16) --------------------
// grid = (4 N-tiles, 32 K-splits), 256 threads (8 warps, 4x2 warp grid).
// smem: A planes [0,64K) (hi|lo 32K each), B planes [64K,128K).
#define SM_B_OFF 65536
#define SMEM_TOTAL 131072

__global__ void __launch_bounds__(256, 1) gemm_kernel()
{
    extern __shared__ char smem[];
    const uint32_t sb = smem_u32(smem);
    const int tid  = threadIdx.x;
    const int lane = tid & 31;
    const int wid  = tid >> 5;
    const int wm   = (wid & 3) * 32;      // warp M offset (0..96)
    const int wn   = (wid >> 2) * 64;     // warp N offset (0 or 64)
    const int ntb  = blockIdx.x * 128;    // N-tile base row in B table
    const int g0   = blockIdx.y * KSLICE; // K slice base

    float acc[2][8][4];
    #pragma unroll
    for (int mf = 0; mf < 2; ++mf)
        #pragma unroll
        for (int nf = 0; nf < 8; ++nf)
            #pragma unroll
            for (int q = 0; q < 4; ++q) acc[mf][nf][q] = 0.f;

    // lane-dependent ldmatrix address components
    const int matA = lane >> 3;
    const int arow = (lane & 7) + ((matA & 1) << 3);  // + wm + mf*16
    const int acadd = matA >> 1;                       // 16B-col add
    const int brow = (lane & 7) + ((matA >> 1) << 3);  // + wn + bq*16
    const int bcadd = matA & 1;

    for (int ck = 0; ck < KSLICE / KCHUNK; ++ck) {
        const int kb = g0 + ck * KCHUNK;
        // ---- load chunk: A 2 planes (128r x 16c of 16B) = 4096 chunks,
        //      then B 2 planes = 4096 chunks. 8192 total -> 32 iters of 256.
        #pragma unroll
        for (int it = 0; it < 32; ++it) {
            int i = it * 256 + tid;            // 0..8191
            if (i < 4096) {
                int plane = (i >> 11) & 1;
                int r = (i >> 4) & 127, c = i & 15;
                const uint4* src = reinterpret_cast<const uint4*>(
                    (plane ? d_Alo : d_Ahi) + (size_t)r * NMAX + kb + c * 8);
                uint4 v = __ldg(src);
                uint32_t so = sb + plane * 32768 + swz(r, c);
                asm volatile("st.shared.v4.b32 [%0], {%1,%2,%3,%4};"
                             :: "r"(so), "r"(v.x), "r"(v.y), "r"(v.z), "r"(v.w));
            } else {
                int j = i - 4096;
                int plane = (j >> 11) & 1;
                int r = (j >> 4) & 127, c = j & 15;
                const uint4* src = reinterpret_cast<const uint4*>(
                    (plane ? d_Blo : d_Bhi) + (size_t)(ntb + r) * NMAX + kb + c * 8);
                uint4 v = __ldg(src);
                uint32_t so = sb + SM_B_OFF + plane * 32768 + swz(r, c);
                asm volatile("st.shared.v4.b32 [%0], {%1,%2,%3,%4};"
                             :: "r"(so), "r"(v.x), "r"(v.y), "r"(v.z), "r"(v.w));
            }
        }
        __syncthreads();

        // ---- MMA: 8 k16-steps x 3 plane-pass products
        #pragma unroll
        for (int ks = 0; ks < 8; ++ks) {
            const int c0 = ks * 2;
            uint32_t aAddr[2], bAddr[4];
            #pragma unroll
            for (int mf = 0; mf < 2; ++mf)
                aAddr[mf] = sb + swz(wm + mf * 16 + arow, c0 + acadd);
            #pragma unroll
            for (int bq = 0; bq < 4; ++bq)
                bAddr[bq] = sb + SM_B_OFF + swz(wn + bq * 16 + brow, c0 + bcadd);

            const uint32_t paO[3] = {0u, 0u, 32768u};
            const uint32_t pbO[3] = {0u, 32768u, 0u};
            #pragma unroll
            for (int p = 0; p < 3; ++p) {
                uint32_t a[2][4];
                #pragma unroll
                for (int mf = 0; mf < 2; ++mf)
                    LDSM4(a[mf][0], a[mf][1], a[mf][2], a[mf][3], aAddr[mf] + paO[p]);
                uint32_t b[8][2];
                #pragma unroll
                for (int bq = 0; bq < 4; ++bq) {
                    uint32_t r0, r1, r2, r3;
                    LDSM4(r0, r1, r2, r3, bAddr[bq] + pbO[p]);
                    b[2 * bq][0] = r0; b[2 * bq][1] = r1;
                    b[2 * bq + 1][0] = r2; b[2 * bq + 1][1] = r3;
                }
                #pragma unroll
                for (int mf = 0; mf < 2; ++mf)
                    #pragma unroll
                    for (int nf = 0; nf < 8; ++nf)
                        MMA16816(acc[mf][nf], a[mf], b[nf]);
            }
        }
        __syncthreads();
    }

    // ---- store 128x128 fp32 partial for this split
    float* part = &d_Part[blockIdx.y][0][0];
    #pragma unroll
    for (int mf = 0; mf < 2; ++mf) {
        #pragma unroll
        for (int nf = 0; nf < 8; ++nf) {
            int row = wm + mf * 16 + (lane >> 2);
            int cc  = ntb + wn + nf * 8 + (lane & 3) * 2;
            float2 v0 = make_float2(acc[mf][nf][0], acc[mf][nf][1]);
            float2 v1 = make_float2(acc[mf][nf][2], acc[mf][nf][3]);
            *reinterpret_cast<float2*>(part + (size_t)row * 512 + cc)       = v0;
            *reinterpret_cast<float2*>(part + (size_t)(row + 8) * 512 + cc) = v1;
        }
    }
}

// ---------------- finalize: reduce splits, divide, tile-scatter --------------
__global__ void __launch_bounds__(256) finalize_kernel(
    float* __restrict__ out, const int* __restrict__ tileHW,
    const int* __restrict__ chunkG, int N)
{
    int p = blockIdx.x * blockDim.x + threadIdx.x;
    if (p >= HH * WW) return;
    int y = p >> 7, x = p & 127;

    float r = 0.f, g = 0.f, b = 0.f, d = 0.f;
    #pragma unroll
    for (int s = 0; s < NSPLIT; ++s) {
        r += d_Part[s][y][x];
        g += d_Part[s][y][128 + x];
        b += d_Part[s][y][256 + x];
        d += d_Part[s][y][384 + x];
    }

    int cg = chunkG[0];
    if (cg <= 0 || cg > N) cg = N;
    d += (float)(N / cg) * EPSc;

    int tw = tileHW[0];
    if (tw <= 0 || tw > 128) tw = 64;
    int step = tw * tw;
    int t = p / step;
    int q = p - t * step;

    float inv = __fdividef(1.f, d);
    float* o = out + (size_t)t * 3 * step + q;
    o[0]        = r * inv;
    o[step]     = g * inv;
    o[2 * step] = b * inv;
}

// ---------------- launch -----------------------------------------------------
extern "C" void kernel_launch(void* const* d_in, const int* in_sizes, int n_in,
                              void* d_out, int out_size)
{
    const float* pos = (const float*)d_in[0];
    const float* col = (const float*)d_in[1];
    const float* opa = (const float*)d_in[2];
    const float* sca = (const float*)d_in[3];
    const float* qv  = (const float*)d_in[4];
    const float* tv  = (const float*)d_in[5];
    const int*   tHW = (n_in > 6) ? (const int*)d_in[6] : nullptr;
    const int*   cG  = (n_in > 7) ? (const int*)d_in[7] : nullptr;

    int N = in_sizes[0] / 3;
    if (N > NMAX) N = NMAX;

    prep_kernel<<<NMAX / 128, 32>>>(pos, col, opa, sca, qv, tv);

    cudaFuncSetAttribute(gemm_kernel, cudaFuncAttributeMaxDynamicSharedMemorySize, SMEM_TOTAL);
    gemm_kernel<<<dim3(4, NSPLIT), 256, SMEM_TOTAL>>>();

    finalize_kernel<<<(HH * WW + 255) / 256, 256>>>((float*)d_out, tHW, cG, N);
}

// round 6
// speedup vs baseline: 2.5554x; 1.4410x over previous
#include <cuda_runtime.h>
#include <cuda_bf16.h>
#include <cstdint>

#define HH   128
#define WW   128
#define NMAX 16384
#define NSPLIT 32
#define KSLICE (NMAX / NSPLIT)       /* 512 */
#define KCHUNK 128
#define FXc 128.0f
#define FYc 128.0f
#define CXc 64.0f
#define CYc 64.0f
#define EPSc 1e-8f

// ---------------- static device scratch (no allocation allowed) -------------
// A = Ey [128 y][K g], B = weighted Ex [512 n][K], n = ch*128 + x,
// ch in {R,G,B,opacity}. Split-bf16 planes (hi/lo).
__device__ __nv_bfloat16 d_Ahi[(size_t)128 * NMAX];
__device__ __nv_bfloat16 d_Alo[(size_t)128 * NMAX];
__device__ __nv_bfloat16 d_Bhi[(size_t)512 * NMAX];
__device__ __nv_bfloat16 d_Blo[(size_t)512 * NMAX];
__device__ float         d_Part[NSPLIT][128][512];   // split-K partials (8 MB)

// ---------------- PTX helpers ------------------------------------------------
__device__ __forceinline__ uint32_t smem_u32(const void* p) {
    uint32_t a;
    asm("{ .reg .u64 t; cvta.to.shared.u64 t, %1; cvt.u32.u64 %0, t; }" : "=r"(a) : "l"(p));
    return a;
}
#define LDSM4(r0, r1, r2, r3, addr)                                          \
    asm volatile("ldmatrix.sync.aligned.m8n8.x4.shared.b16 {%0,%1,%2,%3}, [%4];" \
        : "=r"(r0), "=r"(r1), "=r"(r2), "=r"(r3) : "r"(addr))
#define MMA16816(d, a, b)                                                    \
    asm volatile("mma.sync.aligned.m16n8k16.row.col.f32.bf16.bf16.f32 "      \
        "{%0,%1,%2,%3}, {%4,%5,%6,%7}, {%8,%9}, {%0,%1,%2,%3};"              \
        : "+f"((d)[0]), "+f"((d)[1]), "+f"((d)[2]), "+f"((d)[3])             \
        : "r"((a)[0]), "r"((a)[1]), "r"((a)[2]), "r"((a)[3]),                \
          "r"((b)[0]), "r"((b)[1]))
#define CPASYNC16(so, src)                                                   \
    asm volatile("cp.async.cg.shared.global [%0], [%1], 16;"                 \
        :: "r"(so), "l"(src) : "memory")

// swizzled smem byte offset: row stride 256B (128 bf16), 16B-unit column c
__device__ __forceinline__ uint32_t swz(int r, int c) {
    return (uint32_t)(r * 256 + ((((c) & 8) | (((c) ^ (r)) & 7)) << 4));
}

__device__ __forceinline__ uint32_t pkbf(float a, float b) {
    __nv_bfloat162 h = __floats2bfloat162_rn(a, b);
    uint32_t u;
    memcpy(&u, &h, 4);
    return u;
}

// write 4 consecutive-g values to hi/lo planes with one STG.64 each
__device__ __forceinline__ void st4(__nv_bfloat16* __restrict__ hi,
                                    __nv_bfloat16* __restrict__ lo,
                                    size_t idx, float v0, float v1, float v2, float v3) {
    __nv_bfloat16 h0 = __float2bfloat16_rn(v0);
    __nv_bfloat16 h1 = __float2bfloat16_rn(v1);
    __nv_bfloat16 h2 = __float2bfloat16_rn(v2);
    __nv_bfloat16 h3 = __float2bfloat16_rn(v3);
    uint2 H;
    H.x = pkbf(__bfloat162float(h0), __bfloat162float(h1));
    H.y = pkbf(__bfloat162float(h2), __bfloat162float(h3));
    *reinterpret_cast<uint2*>(hi + idx) = H;
    uint2 L;
    L.x = pkbf(v0 - __bfloat162float(h0), v1 - __bfloat162float(h1));
    L.y = pkbf(v2 - __bfloat162float(h2), v3 - __bfloat162float(h3));
    *reinterpret_cast<uint2*>(lo + idx) = L;
}

// ---------------- prep: project + geometric-recurrence exp tables -----------
// 128 blocks x 256 threads. Thread = (gaussian-quad tid%32, 16-px segment
// tid/32). Each thread recomputes its quad's projection and fills only its
// segment of the x (B) and y (A) tables. Warp lanes span 32 consecutive
// quads -> 256B-contiguous warp stores.
__global__ void __launch_bounds__(256) prep_kernel(
    const float* __restrict__ pos, const float* __restrict__ col,
    const float* __restrict__ opa, const float* __restrict__ sca,
    const float* __restrict__ qv,  const float* __restrict__ tv)
{
    const int gq  = threadIdx.x & 31;
    const int seg = threadIdx.x >> 5;        // 0..7
    const int g0  = (blockIdx.x * 32 + gq) * 4;

    float qw = qv[0], qx = qv[1], qy = qv[2], qz = qv[3];
    float qn = rsqrtf(qw * qw + qx * qx + qy * qy + qz * qz);
    qw *= qn; qx *= qn; qy *= qn; qz *= qn;
    float r00 = 1.f - 2.f * (qy * qy + qz * qz), r01 = 2.f * (qx * qy - qz * qw), r02 = 2.f * (qx * qz + qy * qw);
    float r10 = 2.f * (qx * qy + qz * qw), r11 = 1.f - 2.f * (qx * qx + qz * qz), r12 = 2.f * (qy * qz - qx * qw);
    float r20 = 2.f * (qx * qz - qy * qw), r21 = 2.f * (qy * qz + qx * qw), r22 = 1.f - 2.f * (qx * qx + qy * qy);
    float t0 = tv[0], t1 = tv[1], t2 = tv[2];

    float px[4], py[4], ee[4], q2e[4], oo[4], ocr[4], ocg[4], ocb[4];
    #pragma unroll
    for (int j = 0; j < 4; ++j) {
        int g = g0 + j;
        float p0 = pos[3 * g + 0], p1 = pos[3 * g + 1], p2 = pos[3 * g + 2];
        float cx = r00 * p0 + r01 * p1 + r02 * p2 + t0;
        float cy = r10 * p0 + r11 * p1 + r12 * p2 + t1;
        float cz = r20 * p0 + r21 * p1 + r22 * p2 + t2;
        float invz = __fdividef(1.f, cz);
        px[j] = cx * invz * FXc + CXc;
        py[j] = cy * invz * FYc + CYc;
        float s = sca[g];
        ee[j] = -0.5f * __fdividef(1.f, s * s);
        q2e[j] = __expf(2.f * ee[j]);
        float o = opa[g];
        oo[j]  = o;
        ocr[j] = o * col[3 * g + 0];
        ocg[j] = o * col[3 * g + 1];
        ocb[j] = o * col[3 * g + 2];
    }

    // B rows for this thread's x segment
    {
        const int xb = seg * 16;
        float tx[4], ux[4];
        #pragma unroll
        for (int j = 0; j < 4; ++j) {
            float dx = (float)xb - px[j];
            tx[j] = __expf(ee[j] * dx * dx);
            ux[j] = __expf(ee[j] * (2.f * dx + 1.f));
        }
        #pragma unroll
        for (int k = 0; k < 16; ++k) {
            int x = xb + k;
            st4(d_Bhi, d_Blo, (size_t)(0 * 128 + x) * NMAX + g0,
                tx[0] * ocr[0], tx[1] * ocr[1], tx[2] * ocr[2], tx[3] * ocr[3]);
            st4(d_Bhi, d_Blo, (size_t)(1 * 128 + x) * NMAX + g0,
                tx[0] * ocg[0], tx[1] * ocg[1], tx[2] * ocg[2], tx[3] * ocg[3]);
            st4(d_Bhi, d_Blo, (size_t)(2 * 128 + x) * NMAX + g0,
                tx[0] * ocb[0], tx[1] * ocb[1], tx[2] * ocb[2], tx[3] * ocb[3]);
            st4(d_Bhi, d_Blo, (size_t)(3 * 128 + x) * NMAX + g0,
                tx[0] * oo[0], tx[1] * oo[1], tx[2] * oo[2], tx[3] * oo[3]);
            #pragma unroll
            for (int j = 0; j < 4; ++j) { tx[j] *= ux[j]; ux[j] *= q2e[j]; }
        }
    }
    // A rows for this thread's y segment
    {
        const int yb = seg * 16;
        float ty[4], uy[4];
        #pragma unroll
        for (int j = 0; j < 4; ++j) {
            float dy = (float)yb - py[j];
            ty[j] = __expf(ee[j] * dy * dy);
            uy[j] = __expf(ee[j] * (2.f * dy + 1.f));
        }
        #pragma unroll
        for (int k = 0; k < 16; ++k) {
            st4(d_Ahi, d_Alo, (size_t)(yb + k) * NMAX + g0, ty[0], ty[1], ty[2], ty[3]);
            #pragma unroll
            for (int j = 0; j < 4; ++j) { ty[j] *= uy[j]; uy[j] *= q2e[j]; }
        }
    }
}

// ---------------- GEMM via HMMA (mma.sync m16n8k16 bf16) --------------------
// grid = (4 N-tiles, 32 K-splits), 256 threads (8 warps, 4x2 warp grid).
// smem: A planes [0,64K) (hi|lo 32K each), B planes [64K,128K).
#define SM_B_OFF 65536
#define SMEM_TOTAL 131072

__global__ void __launch_bounds__(256, 1) gemm_kernel()
{
    extern __shared__ char smem[];
    const uint32_t sb = smem_u32(smem);
    const int tid  = threadIdx.x;
    const int lane = tid & 31;
    const int wid  = tid >> 5;
    const int wm   = (wid & 3) * 32;      // warp M offset (0..96)
    const int wn   = (wid >> 2) * 64;     // warp N offset (0 or 64)
    const int ntb  = blockIdx.x * 128;    // N-tile base row in B table
    const int g0   = blockIdx.y * KSLICE; // K slice base

    float acc[2][8][4];
    #pragma unroll
    for (int mf = 0; mf < 2; ++mf)
        #pragma unroll
        for (int nf = 0; nf < 8; ++nf)
            #pragma unroll
            for (int q = 0; q < 4; ++q) acc[mf][nf][q] = 0.f;

    // lane-dependent ldmatrix address components
    const int matA = lane >> 3;
    const int arow = (lane & 7) + ((matA & 1) << 3);  // + wm + mf*16
    const int acadd = matA >> 1;                       // 16B-col add
    const int brow = (lane & 7) + ((matA >> 1) << 3);  // + wn + bq*16
    const int bcadd = matA & 1;

    for (int ck = 0; ck < KSLICE / KCHUNK; ++ck) {
        const int kb = g0 + ck * KCHUNK;
        // ---- async-load chunk: A 2 planes (128r x 16c of 16B) = 4096 chunks,
        //      then B 2 planes = 4096 chunks. 8192 total -> 32 iters of 256.
        #pragma unroll
        for (int it = 0; it < 32; ++it) {
            int i = it * 256 + tid;            // 0..8191
            if (i < 4096) {
                int plane = (i >> 11) & 1;
                int r = (i >> 4) & 127, c = i & 15;
                const void* src = (const void*)(
                    (plane ? d_Alo : d_Ahi) + (size_t)r * NMAX + kb + c * 8);
                uint32_t so = sb + plane * 32768 + swz(r, c);
                CPASYNC16(so, src);
            } else {
                int j = i - 4096;
                int plane = (j >> 11) & 1;
                int r = (j >> 4) & 127, c = j & 15;
                const void* src = (const void*)(
                    (plane ? d_Blo : d_Bhi) + (size_t)(ntb + r) * NMAX + kb + c * 8);
                uint32_t so = sb + SM_B_OFF + plane * 32768 + swz(r, c);
                CPASYNC16(so, src);
            }
        }
        asm volatile("cp.async.commit_group;" ::: "memory");
        asm volatile("cp.async.wait_group 0;" ::: "memory");
        __syncthreads();

        // ---- MMA: 8 k16-steps x 3 plane-pass products
        #pragma unroll
        for (int ks = 0; ks < 8; ++ks) {
            const int c0 = ks * 2;
            uint32_t aAddr[2], bAddr[4];
            #pragma unroll
            for (int mf = 0; mf < 2; ++mf)
                aAddr[mf] = sb + swz(wm + mf * 16 + arow, c0 + acadd);
            #pragma unroll
            for (int bq = 0; bq < 4; ++bq)
                bAddr[bq] = sb + SM_B_OFF + swz(wn + bq * 16 + brow, c0 + bcadd);

            const uint32_t paO[3] = {0u, 0u, 32768u};
            const uint32_t pbO[3] = {0u, 32768u, 0u};
            #pragma unroll
            for (int p = 0; p < 3; ++p) {
                uint32_t a[2][4];
                #pragma unroll
                for (int mf = 0; mf < 2; ++mf)
                    LDSM4(a[mf][0], a[mf][1], a[mf][2], a[mf][3], aAddr[mf] + paO[p]);
                uint32_t b[8][2];
                #pragma unroll
                for (int bq = 0; bq < 4; ++bq) {
                    uint32_t r0, r1, r2, r3;
                    LDSM4(r0, r1, r2, r3, bAddr[bq] + pbO[p]);
                    b[2 * bq][0] = r0; b[2 * bq][1] = r1;
                    b[2 * bq + 1][0] = r2; b[2 * bq + 1][1] = r3;
                }
                #pragma unroll
                for (int mf = 0; mf < 2; ++mf)
                    #pragma unroll
                    for (int nf = 0; nf < 8; ++nf)
                        MMA16816(acc[mf][nf], a[mf], b[nf]);
            }
        }
        __syncthreads();
    }

    // ---- store 128x128 fp32 partial for this split
    float* part = &d_Part[blockIdx.y][0][0];
    #pragma unroll
    for (int mf = 0; mf < 2; ++mf) {
        #pragma unroll
        for (int nf = 0; nf < 8; ++nf) {
            int row = wm + mf * 16 + (lane >> 2);
            int cc  = ntb + wn + nf * 8 + (lane & 3) * 2;
            float2 v0 = make_float2(acc[mf][nf][0], acc[mf][nf][1]);
            float2 v1 = make_float2(acc[mf][nf][2], acc[mf][nf][3]);
            *reinterpret_cast<float2*>(part + (size_t)row * 512 + cc)       = v0;
            *reinterpret_cast<float2*>(part + (size_t)(row + 8) * 512 + cc) = v1;
        }
    }
}

// ---------------- finalize: reduce splits, divide, tile-scatter --------------
__global__ void __launch_bounds__(256) finalize_kernel(
    float* __restrict__ out, const int* __restrict__ tileHW,
    const int* __restrict__ chunkG, int N)
{
    int p = blockIdx.x * blockDim.x + threadIdx.x;
    if (p >= HH * WW) return;
    int y = p >> 7, x = p & 127;

    float r = 0.f, g = 0.f, b = 0.f, d = 0.f;
    #pragma unroll
    for (int s = 0; s < NSPLIT; ++s) {
        r += d_Part[s][y][x];
        g += d_Part[s][y][128 + x];
        b += d_Part[s][y][256 + x];
        d += d_Part[s][y][384 + x];
    }

    int cg = chunkG[0];
    if (cg <= 0 || cg > N) cg = N;
    d += (float)(N / cg) * EPSc;

    int tw = tileHW[0];
    if (tw <= 0 || tw > 128) tw = 64;
    int step = tw * tw;
    int t = p / step;
    int q = p - t * step;

    float inv = __fdividef(1.f, d);
    float* o = out + (size_t)t * 3 * step + q;
    o[0]        = r * inv;
    o[step]     = g * inv;
    o[2 * step] = b * inv;
}

// ---------------- launch -----------------------------------------------------
extern "C" void kernel_launch(void* const* d_in, const int* in_sizes, int n_in,
                              void* d_out, int out_size)
{
    const float* pos = (const float*)d_in[0];
    const float* col = (const float*)d_in[1];
    const float* opa = (const float*)d_in[2];
    const float* sca = (const float*)d_in[3];
    const float* qv  = (const float*)d_in[4];
    const float* tv  = (const float*)d_in[5];
    const int*   tHW = (n_in > 6) ? (const int*)d_in[6] : nullptr;
    const int*   cG  = (n_in > 7) ? (const int*)d_in[7] : nullptr;

    int N = in_sizes[0] / 3;
    if (N > NMAX) N = NMAX;

    prep_kernel<<<NMAX / 128, 256>>>(pos, col, opa, sca, qv, tv);

    cudaFuncSetAttribute(gemm_kernel, cudaFuncAttributeMaxDynamicSharedMemorySize, SMEM_TOTAL);
    gemm_kernel<<<dim3(4, NSPLIT), 256, SMEM_TOTAL>>>();

    finalize_kernel<<<(HH * WW + 255) / 256, 256>>>((float*)d_out, tHW, cG, N);
}

// round 9
// speedup vs baseline: 2.9088x; 1.1383x over previous
#include <cuda_runtime.h>
#include <cuda_bf16.h>
#include <cstdint>

#define HH   128
#define WW   128
#define NMAX 16384
#define NSPLIT 32
#define KSLICE (NMAX / NSPLIT)       /* 512 */
#define KCHUNK 128
#define FXc 128.0f
#define FYc 128.0f
#define CXc 64.0f
#define CYc 64.0f
#define EPSc 1e-8f

// ---------------- static device scratch (no allocation allowed) -------------
// A = Ey [128 y][K g], B = weighted Ex [512 n][K], n = ch*128 + x,
// ch in {R,G,B,opacity}. Plain bf16 (error analysis: unbiased per-term
// rounding averages out over ~1500 effective gaussians per pixel).
__device__ __nv_bfloat16 d_A[(size_t)128 * NMAX];
__device__ __nv_bfloat16 d_B[(size_t)512 * NMAX];
__device__ float         d_Part[NSPLIT][128][512];   // split-K partials (8 MB)

// ---------------- PTX helpers ------------------------------------------------
__device__ __forceinline__ uint32_t smem_u32(const void* p) {
    uint32_t a;
    asm("{ .reg .u64 t; cvta.to.shared.u64 t, %1; cvt.u32.u64 %0, t; }" : "=r"(a) : "l"(p));
    return a;
}
#define LDSM4(r0, r1, r2, r3, addr)                                          \
    asm volatile("ldmatrix.sync.aligned.m8n8.x4.shared.b16 {%0,%1,%2,%3}, [%4];" \
        : "=r"(r0), "=r"(r1), "=r"(r2), "=r"(r3) : "r"(addr))
#define MMA16816(d, a, b)                                                    \
    asm volatile("mma.sync.aligned.m16n8k16.row.col.f32.bf16.bf16.f32 "      \
        "{%0,%1,%2,%3}, {%4,%5,%6,%7}, {%8,%9}, {%0,%1,%2,%3};"              \
        : "+f"((d)[0]), "+f"((d)[1]), "+f"((d)[2]), "+f"((d)[3])             \
        : "r"((a)[0]), "r"((a)[1]), "r"((a)[2]), "r"((a)[3]),                \
          "r"((b)[0]), "r"((b)[1]))
#define CPASYNC16(so, src)                                                   \
    asm volatile("cp.async.cg.shared.global [%0], [%1], 16;"                 \
        :: "r"(so), "l"(src) : "memory")

// swizzled smem byte offset: row stride 256B (128 bf16), 16B-unit column c
__device__ __forceinline__ uint32_t swz(int r, int c) {
    return (uint32_t)(r * 256 + ((((c) & 8) | (((c) ^ (r)) & 7)) << 4));
}

__device__ __forceinline__ uint32_t pkbf(float a, float b) {
    __nv_bfloat162 h = __floats2bfloat162_rn(a, b);
    uint32_t u;
    memcpy(&u, &h, 4);
    return u;
}

// write 4 consecutive-g bf16 values with one STG.64
__device__ __forceinline__ void st4h(__nv_bfloat16* __restrict__ t, size_t idx,
                                     float v0, float v1, float v2, float v3) {
    uint2 H;
    H.x = pkbf(v0, v1);
    H.y = pkbf(v2, v3);
    *reinterpret_cast<uint2*>(t + idx) = H;
}

// ---------------- prep: project + geometric-recurrence exp tables -----------
// 128 blocks x 512 threads. Thread = (gaussian-quad tid%32, 8-px segment
// tid/32, 16 segments). Each thread recomputes its quad's projection and
// fills only its segment. Warp lanes span 32 consecutive quads ->
// 256B-contiguous warp stores.
__global__ void __launch_bounds__(512) prep_kernel(
    const float* __restrict__ pos, const float* __restrict__ col,
    const float* __restrict__ opa, const float* __restrict__ sca,
    const float* __restrict__ qv,  const float* __restrict__ tv)
{
    const int gq  = threadIdx.x & 31;
    const int seg = threadIdx.x >> 5;        // 0..15
    const int g0  = (blockIdx.x * 32 + gq) * 4;

    float qw = qv[0], qx = qv[1], qy = qv[2], qz = qv[3];
    float qn = rsqrtf(qw * qw + qx * qx + qy * qy + qz * qz);
    qw *= qn; qx *= qn; qy *= qn; qz *= qn;
    float r00 = 1.f - 2.f * (qy * qy + qz * qz), r01 = 2.f * (qx * qy - qz * qw), r02 = 2.f * (qx * qz + qy * qw);
    float r10 = 2.f * (qx * qy + qz * qw), r11 = 1.f - 2.f * (qx * qx + qz * qz), r12 = 2.f * (qy * qz - qx * qw);
    float r20 = 2.f * (qx * qz - qy * qw), r21 = 2.f * (qy * qz + qx * qw), r22 = 1.f - 2.f * (qx * qx + qy * qy);
    float t0 = tv[0], t1 = tv[1], t2 = tv[2];

    float px[4], py[4], ee[4], q2e[4], oo[4], ocr[4], ocg[4], ocb[4];
    #pragma unroll
    for (int j = 0; j < 4; ++j) {
        int g = g0 + j;
        float p0 = pos[3 * g + 0], p1 = pos[3 * g + 1], p2 = pos[3 * g + 2];
        float cx = r00 * p0 + r01 * p1 + r02 * p2 + t0;
        float cy = r10 * p0 + r11 * p1 + r12 * p2 + t1;
        float cz = r20 * p0 + r21 * p1 + r22 * p2 + t2;
        float invz = __fdividef(1.f, cz);
        px[j] = cx * invz * FXc + CXc;
        py[j] = cy * invz * FYc + CYc;
        float s = sca[g];
        ee[j] = -0.5f * __fdividef(1.f, s * s);
        q2e[j] = __expf(2.f * ee[j]);
        float o = opa[g];
        oo[j]  = o;
        ocr[j] = o * col[3 * g + 0];
        ocg[j] = o * col[3 * g + 1];
        ocb[j] = o * col[3 * g + 2];
    }

    // B rows for this thread's x segment (8 px)
    {
        const int xb = seg * 8;
        float tx[4], ux[4];
        #pragma unroll
        for (int j = 0; j < 4; ++j) {
            float dx = (float)xb - px[j];
            tx[j] = __expf(ee[j] * dx * dx);
            ux[j] = __expf(ee[j] * (2.f * dx + 1.f));
        }
        #pragma unroll
        for (int k = 0; k < 8; ++k) {
            int x = xb + k;
            st4h(d_B, (size_t)(0 * 128 + x) * NMAX + g0,
                 tx[0] * ocr[0], tx[1] * ocr[1], tx[2] * ocr[2], tx[3] * ocr[3]);
            st4h(d_B, (size_t)(1 * 128 + x) * NMAX + g0,
                 tx[0] * ocg[0], tx[1] * ocg[1], tx[2] * ocg[2], tx[3] * ocg[3]);
            st4h(d_B, (size_t)(2 * 128 + x) * NMAX + g0,
                 tx[0] * ocb[0], tx[1] * ocb[1], tx[2] * ocb[2], tx[3] * ocb[3]);
            st4h(d_B, (size_t)(3 * 128 + x) * NMAX + g0,
                 tx[0] * oo[0], tx[1] * oo[1], tx[2] * oo[2], tx[3] * oo[3]);
            #pragma unroll
            for (int j = 0; j < 4; ++j) { tx[j] *= ux[j]; ux[j] *= q2e[j]; }
        }
    }
    // A rows for this thread's y segment (8 px)
    {
        const int yb = seg * 8;
        float ty[4], uy[4];
        #pragma unroll
        for (int j = 0; j < 4; ++j) {
            float dy = (float)yb - py[j];
            ty[j] = __expf(ee[j] * dy * dy);
            uy[j] = __expf(ee[j] * (2.f * dy + 1.f));
        }
        #pragma unroll
        for (int k = 0; k < 8; ++k) {
            st4h(d_A, (size_t)(yb + k) * NMAX + g0, ty[0], ty[1], ty[2], ty[3]);
            #pragma unroll
            for (int j = 0; j < 4; ++j) { ty[j] *= uy[j]; uy[j] *= q2e[j]; }
        }
    }
}

// ---------------- GEMM via HMMA, double-buffered ----------------------------
// grid = (4 N-tiles, 32 K-splits), 256 threads (8 warps, 4x2 warp grid).
// Stage = 64KB: A tile [0,32K), B tile [32K,64K). 2 stages = 128KB.
#define STAGE_BYTES 65536
#define SM_B_OFF 32768
#define SMEM_TOTAL 131072

__global__ void __launch_bounds__(256, 1) gemm_kernel()
{
    extern __shared__ char smem[];
    const uint32_t sb = smem_u32(smem);
    const int tid  = threadIdx.x;
    const int lane = tid & 31;
    const int wid  = tid >> 5;
    const int wm   = (wid & 3) * 32;      // warp M offset (0..96)
    const int wn   = (wid >> 2) * 64;     // warp N offset (0 or 64)
    const int ntb  = blockIdx.x * 128;    // N-tile base row in B table
    const int g0   = blockIdx.y * KSLICE; // K slice base

    float acc[2][8][4];
    #pragma unroll
    for (int mf = 0; mf < 2; ++mf)
        #pragma unroll
        for (int nf = 0; nf < 8; ++nf)
            #pragma unroll
            for (int q = 0; q < 4; ++q) acc[mf][nf][q] = 0.f;

    // lane-dependent ldmatrix address components
    const int matA = lane >> 3;
    const int arow = (lane & 7) + ((matA & 1) << 3);
    const int acadd = matA >> 1;
    const int brow = (lane & 7) + ((matA >> 1) << 3);
    const int bcadd = matA & 1;

    // load of one chunk into stage s: 2048 A + 2048 B 16B-chunks, 16/thread
    auto load_chunk = [&](int s, int ck) {
        const int kb = g0 + ck * KCHUNK;
        const uint32_t st = sb + s * STAGE_BYTES;
        #pragma unroll
        for (int it = 0; it < 16; ++it) {
            int i = it * 256 + tid;            // 0..4095
            int r = (i >> 4) & 127, c = i & 15;
            if (i < 2048) {
                const void* src = (const void*)(d_A + (size_t)r * NMAX + kb + c * 8);
                CPASYNC16(st + swz(r, c), src);
            } else {
                const void* src = (const void*)(d_B + (size_t)(ntb + r) * NMAX + kb + c * 8);
                CPASYNC16(st + SM_B_OFF + swz(r, c), src);
            }
        }
        asm volatile("cp.async.commit_group;" ::: "memory");
    };

    load_chunk(0, 0);

    const int NCHUNK = KSLICE / KCHUNK;   // 4
    for (int ck = 0; ck < NCHUNK; ++ck) {
        if (ck + 1 < NCHUNK) load_chunk((ck + 1) & 1, ck + 1);
        if (ck + 1 < NCHUNK)
            asm volatile("cp.async.wait_group 1;" ::: "memory");
        else
            asm volatile("cp.async.wait_group 0;" ::: "memory");
        __syncthreads();

        const uint32_t st = sb + (ck & 1) * STAGE_BYTES;
        #pragma unroll
        for (int ks = 0; ks < 8; ++ks) {
            const int c0 = ks * 2;
            uint32_t a[2][4];
            #pragma unroll
            for (int mf = 0; mf < 2; ++mf)
                LDSM4(a[mf][0], a[mf][1], a[mf][2], a[mf][3],
                      st + swz(wm + mf * 16 + arow, c0 + acadd));
            uint32_t b[8][2];
            #pragma unroll
            for (int bq = 0; bq < 4; ++bq) {
                uint32_t r0, r1, r2, r3;
                LDSM4(r0, r1, r2, r3,
                      st + SM_B_OFF + swz(wn + bq * 16 + brow, c0 + bcadd));
                b[2 * bq][0] = r0; b[2 * bq][1] = r1;
                b[2 * bq + 1][0] = r2; b[2 * bq + 1][1] = r3;
            }
            #pragma unroll
            for (int mf = 0; mf < 2; ++mf)
                #pragma unroll
                for (int nf = 0; nf < 8; ++nf)
                    MMA16816(acc[mf][nf], a[mf], b[nf]);
        }
        __syncthreads();
    }

    // ---- store 128x128 fp32 partial for this split
    float* part = &d_Part[blockIdx.y][0][0];
    #pragma unroll
    for (int mf = 0; mf < 2; ++mf) {
        #pragma unroll
        for (int nf = 0; nf < 8; ++nf) {
            int row = wm + mf * 16 + (lane >> 2);
            int cc  = ntb + wn + nf * 8 + (lane & 3) * 2;
            float2 v0 = make_float2(acc[mf][nf][0], acc[mf][nf][1]);
            float2 v1 = make_float2(acc[mf][nf][2], acc[mf][nf][3]);
            *reinterpret_cast<float2*>(part + (size_t)row * 512 + cc)       = v0;
            *reinterpret_cast<float2*>(part + (size_t)(row + 8) * 512 + cc) = v1;
        }
    }
}

// ---------------- finalize: reduce splits, divide, tile-scatter --------------
__global__ void __launch_bounds__(256) finalize_kernel(
    float* __restrict__ out, const int* __restrict__ tileHW,
    const int* __restrict__ chunkG, int N)
{
    int p = blockIdx.x * blockDim.x + threadIdx.x;
    if (p >= HH * WW) return;
    int y = p >> 7, x = p & 127;

    float r = 0.f, g = 0.f, b = 0.f, d = 0.f;
    #pragma unroll
    for (int s = 0; s < NSPLIT; ++s) {
        r += d_Part[s][y][x];
        g += d_Part[s][y][128 + x];
        b += d_Part[s][y][256 + x];
        d += d_Part[s][y][384 + x];
    }

    int cg = chunkG[0];
    if (cg <= 0 || cg > N) cg = N;
    d += (float)(N / cg) * EPSc;

    int tw = tileHW[0];
    if (tw <= 0 || tw > 128) tw = 64;
    int step = tw * tw;
    int t = p / step;
    int q = p - t * step;

    float inv = __fdividef(1.f, d);
    float* o = out + (size_t)t * 3 * step + q;
    o[0]        = r * inv;
    o[step]     = g * inv;
    o[2 * step] = b * inv;
}

// ---------------- launch -----------------------------------------------------
extern "C" void kernel_launch(void* const* d_in, const int* in_sizes, int n_in,
                              void* d_out, int out_size)
{
    const float* pos = (const float*)d_in[0];
    const float* col = (const float*)d_in[1];
    const float* opa = (const float*)d_in[2];
    const float* sca = (const float*)d_in[3];
    const float* qv  = (const float*)d_in[4];
    const float* tv  = (const float*)d_in[5];
    const int*   tHW = (n_in > 6) ? (const int*)d_in[6] : nullptr;
    const int*   cG  = (n_in > 7) ? (const int*)d_in[7] : nullptr;

    int N = in_sizes[0] / 3;
    if (N > NMAX) N = NMAX;

    prep_kernel<<<NMAX / 128, 512>>>(pos, col, opa, sca, qv, tv);

    cudaFuncSetAttribute(gemm_kernel, cudaFuncAttributeMaxDynamicSharedMemorySize, SMEM_TOTAL);
    gemm_kernel<<<dim3(4, NSPLIT), 256, SMEM_TOTAL>>>();

    finalize_kernel<<<(HH * WW + 255) / 256, 256>>>((float*)d_out, tHW, cG, N);
}

// round 10
// speedup vs baseline: 4.3344x; 1.4901x over previous
#include <cuda_runtime.h>
#include <cuda_bf16.h>
#include <cstdint>

#define HH   128
#define WW   128
#define NMAX 16384
#define NSPLIT 32
#define KSLICE (NMAX / NSPLIT)       /* 512 */
#define KCHUNK 128
#define FXc 128.0f
#define FYc 128.0f
#define CXc 64.0f
#define CYc 64.0f
#define EPSc 1e-8f

// ---------------- static device scratch (no allocation allowed) -------------
// A = Ey [128 y][K g], B = weighted Ex [512 n][K], n = ch*128 + x.
__device__ __nv_bfloat16 d_A[(size_t)128 * NMAX];
__device__ __nv_bfloat16 d_B[(size_t)512 * NMAX];
__device__ float         d_Part[NSPLIT][128][512];   // split-K partials (8 MB)

// ---------------- PTX helpers ------------------------------------------------
__device__ __forceinline__ uint32_t smem_u32(const void* p) {
    uint32_t a;
    asm("{ .reg .u64 t; cvta.to.shared.u64 t, %1; cvt.u32.u64 %0, t; }" : "=r"(a) : "l"(p));
    return a;
}
#define LDSM4(r0, r1, r2, r3, addr)                                          \
    asm volatile("ldmatrix.sync.aligned.m8n8.x4.shared.b16 {%0,%1,%2,%3}, [%4];" \
        : "=r"(r0), "=r"(r1), "=r"(r2), "=r"(r3) : "r"(addr))
#define MMA16816(d, a, b)                                                    \
    asm volatile("mma.sync.aligned.m16n8k16.row.col.f32.bf16.bf16.f32 "      \
        "{%0,%1,%2,%3}, {%4,%5,%6,%7}, {%8,%9}, {%0,%1,%2,%3};"              \
        : "+f"((d)[0]), "+f"((d)[1]), "+f"((d)[2]), "+f"((d)[3])             \
        : "r"((a)[0]), "r"((a)[1]), "r"((a)[2]), "r"((a)[3]),                \
          "r"((b)[0]), "r"((b)[1]))
#define CPASYNC16(so, src)                                                   \
    asm volatile("cp.async.cg.shared.global [%0], [%1], 16;"                 \
        :: "r"(so), "l"(src) : "memory")
#define MULBF2(res, a, b) \
    asm("mul.bf16x2 %0, %1, %2;" : "=r"(res) : "r"(a), "r"(b))

// packed f32x2 helpers
__device__ __forceinline__ unsigned long long f2pack(float a, float b) {
    unsigned long long r;
    asm("mov.b64 %0, {%1, %2};" : "=l"(r) : "f"(a), "f"(b));
    return r;
}
__device__ __forceinline__ void f2unpack(unsigned long long v, float& a, float& b) {
    asm("mov.b64 {%0, %1}, %2;" : "=f"(a), "=f"(b) : "l"(v));
}
__device__ __forceinline__ unsigned long long f2mul(unsigned long long a, unsigned long long b) {
    unsigned long long r;
    asm("mul.rn.f32x2 %0, %1, %2;" : "=l"(r) : "l"(a), "l"(b));
    return r;
}

// swizzled smem byte offset: row stride 256B (128 bf16), 16B-unit column c
__device__ __forceinline__ uint32_t swz(int r, int c) {
    return (uint32_t)(r * 256 + ((((c) & 8) | (((c) ^ (r)) & 7)) << 4));
}

__device__ __forceinline__ uint32_t pkbf(float a, float b) {
    __nv_bfloat162 h = __floats2bfloat162_rn(a, b);
    uint32_t u;
    memcpy(&u, &h, 4);
    return u;
}

// ---------------- prep v3: shared preamble + packed math --------------------
// 128 blocks x 1024 threads. Phase 1: tid<128 computes per-gaussian params
// into smem. Phase 2: thread = (quad tid%32, 4-px segment tid/32).
__global__ void __launch_bounds__(1024) prep_kernel(
    const float* __restrict__ pos, const float* __restrict__ col,
    const float* __restrict__ opa, const float* __restrict__ sca,
    const float* __restrict__ qv,  const float* __restrict__ tv)
{
    __shared__ float sPx[128], sPy[128], sEe[128], sQ2[128];
    __shared__ float sCr[128], sCg[128], sCb[128], sOo[128];

    const int tid = threadIdx.x;

    if (tid < 128) {
        int g = blockIdx.x * 128 + tid;
        float qw = qv[0], qx = qv[1], qy = qv[2], qz = qv[3];
        float qn = rsqrtf(qw * qw + qx * qx + qy * qy + qz * qz);
        qw *= qn; qx *= qn; qy *= qn; qz *= qn;
        float r00 = 1.f - 2.f * (qy * qy + qz * qz), r01 = 2.f * (qx * qy - qz * qw), r02 = 2.f * (qx * qz + qy * qw);
        float r10 = 2.f * (qx * qy + qz * qw), r11 = 1.f - 2.f * (qx * qx + qz * qz), r12 = 2.f * (qy * qz - qx * qw);
        float r20 = 2.f * (qx * qz - qy * qw), r21 = 2.f * (qy * qz + qx * qw), r22 = 1.f - 2.f * (qx * qx + qy * qy);

        float p0 = pos[3 * g + 0], p1 = pos[3 * g + 1], p2 = pos[3 * g + 2];
        float cx = r00 * p0 + r01 * p1 + r02 * p2 + tv[0];
        float cy = r10 * p0 + r11 * p1 + r12 * p2 + tv[1];
        float cz = r20 * p0 + r21 * p1 + r22 * p2 + tv[2];
        float invz = __fdividef(1.f, cz);
        sPx[tid] = cx * invz * FXc + CXc;
        sPy[tid] = cy * invz * FYc + CYc;
        float s = sca[g];
        float e = -0.5f * __fdividef(1.f, s * s);
        sEe[tid] = e;
        sQ2[tid] = __expf(2.f * e);
        float o = opa[g];
        sOo[tid] = o;
        sCr[tid] = o * col[3 * g + 0];
        sCg[tid] = o * col[3 * g + 1];
        sCb[tid] = o * col[3 * g + 2];
    }
    __syncthreads();

    const int gq  = tid & 31;
    const int seg = tid >> 5;            // 0..31 -> 4-px segment
    const int gl  = gq * 4;              // local gaussian base
    const int g0  = blockIdx.x * 128 + gl;
    const int pb  = seg * 4;

    const float e0 = sEe[gl + 0], e1 = sEe[gl + 1], e2 = sEe[gl + 2], e3 = sEe[gl + 3];
    const unsigned long long q01 = f2pack(sQ2[gl + 0], sQ2[gl + 1]);
    const unsigned long long q23 = f2pack(sQ2[gl + 2], sQ2[gl + 3]);
    const float px0 = sPx[gl + 0], px1 = sPx[gl + 1], px2 = sPx[gl + 2], px3 = sPx[gl + 3];
    const float py0 = sPy[gl + 0], py1 = sPy[gl + 1], py2 = sPy[gl + 2], py3 = sPy[gl + 3];

    const uint32_t cr01 = pkbf(sCr[gl + 0], sCr[gl + 1]), cr23 = pkbf(sCr[gl + 2], sCr[gl + 3]);
    const uint32_t cg01 = pkbf(sCg[gl + 0], sCg[gl + 1]), cg23 = pkbf(sCg[gl + 2], sCg[gl + 3]);
    const uint32_t cb01 = pkbf(sCb[gl + 0], sCb[gl + 1]), cb23 = pkbf(sCb[gl + 2], sCb[gl + 3]);
    const uint32_t oo01 = pkbf(sOo[gl + 0], sOo[gl + 1]), oo23 = pkbf(sOo[gl + 2], sOo[gl + 3]);

    // ---- B rows for this segment's 4 x-values ----
    {
        float dx0 = (float)pb - px0, dx1 = (float)pb - px1;
        float dx2 = (float)pb - px2, dx3 = (float)pb - px3;
        unsigned long long t01 = f2pack(__expf(e0 * dx0 * dx0), __expf(e1 * dx1 * dx1));
        unsigned long long t23 = f2pack(__expf(e2 * dx2 * dx2), __expf(e3 * dx3 * dx3));
        unsigned long long u01 = f2pack(__expf(e0 * (2.f * dx0 + 1.f)), __expf(e1 * (2.f * dx1 + 1.f)));
        unsigned long long u23 = f2pack(__expf(e2 * (2.f * dx2 + 1.f)), __expf(e3 * (2.f * dx3 + 1.f)));

        __nv_bfloat16* bp = d_B + (size_t)pb * NMAX + g0;
        #pragma unroll
        for (int k = 0; k < 4; ++k) {
            float a0, a1, a2, a3;
            f2unpack(t01, a0, a1); f2unpack(t23, a2, a3);
            uint32_t p01 = pkbf(a0, a1), p23 = pkbf(a2, a3);
            uint2 v;
            MULBF2(v.x, p01, cr01); MULBF2(v.y, p23, cr23);
            *reinterpret_cast<uint2*>(bp + (size_t)0 * 128 * NMAX) = v;
            MULBF2(v.x, p01, cg01); MULBF2(v.y, p23, cg23);
            *reinterpret_cast<uint2*>(bp + (size_t)1 * 128 * NMAX) = v;
            MULBF2(v.x, p01, cb01); MULBF2(v.y, p23, cb23);
            *reinterpret_cast<uint2*>(bp + (size_t)2 * 128 * NMAX) = v;
            MULBF2(v.x, p01, oo01); MULBF2(v.y, p23, oo23);
            *reinterpret_cast<uint2*>(bp + (size_t)3 * 128 * NMAX) = v;
            t01 = f2mul(t01, u01); u01 = f2mul(u01, q01);
            t23 = f2mul(t23, u23); u23 = f2mul(u23, q23);
            bp += NMAX;
        }
    }
    // ---- A rows for this segment's 4 y-values ----
    {
        float dy0 = (float)pb - py0, dy1 = (float)pb - py1;
        float dy2 = (float)pb - py2, dy3 = (float)pb - py3;
        unsigned long long t01 = f2pack(__expf(e0 * dy0 * dy0), __expf(e1 * dy1 * dy1));
        unsigned long long t23 = f2pack(__expf(e2 * dy2 * dy2), __expf(e3 * dy3 * dy3));
        unsigned long long u01 = f2pack(__expf(e0 * (2.f * dy0 + 1.f)), __expf(e1 * (2.f * dy1 + 1.f)));
        unsigned long long u23 = f2pack(__expf(e2 * (2.f * dy2 + 1.f)), __expf(e3 * (2.f * dy3 + 1.f)));

        __nv_bfloat16* ap = d_A + (size_t)pb * NMAX + g0;
        #pragma unroll
        for (int k = 0; k < 4; ++k) {
            float a0, a1, a2, a3;
            f2unpack(t01, a0, a1); f2unpack(t23, a2, a3);
            uint2 v;
            v.x = pkbf(a0, a1); v.y = pkbf(a2, a3);
            *reinterpret_cast<uint2*>(ap) = v;
            t01 = f2mul(t01, u01); u01 = f2mul(u01, q01);
            t23 = f2mul(t23, u23); u23 = f2mul(u23, q23);
            ap += NMAX;
        }
    }
}

// ---------------- GEMM via HMMA, double-buffered ----------------------------
// grid = (4 N-tiles, 32 K-splits), 256 threads (8 warps, 4x2 warp grid).
// Stage = 64KB: A tile [0,32K), B tile [32K,64K). 2 stages = 128KB.
#define STAGE_BYTES 65536
#define SM_B_OFF 32768
#define SMEM_TOTAL 131072

__global__ void __launch_bounds__(256, 1) gemm_kernel()
{
    extern __shared__ char smem[];
    const uint32_t sb = smem_u32(smem);
    const int tid  = threadIdx.x;
    const int lane = tid & 31;
    const int wid  = tid >> 5;
    const int wm   = (wid & 3) * 32;      // warp M offset (0..96)
    const int wn   = (wid >> 2) * 64;     // warp N offset (0 or 64)
    const int ntb  = blockIdx.x * 128;    // N-tile base row in B table
    const int g0   = blockIdx.y * KSLICE; // K slice base

    float acc[2][8][4];
    #pragma unroll
    for (int mf = 0; mf < 2; ++mf)
        #pragma unroll
        for (int nf = 0; nf < 8; ++nf)
            #pragma unroll
            for (int q = 0; q < 4; ++q) acc[mf][nf][q] = 0.f;

    // lane-dependent ldmatrix address components
    const int matA = lane >> 3;
    const int arow = (lane & 7) + ((matA & 1) << 3);
    const int acadd = matA >> 1;
    const int brow = (lane & 7) + ((matA >> 1) << 3);
    const int bcadd = matA & 1;

    // load of one chunk into stage s: 2048 A + 2048 B 16B-chunks, 16/thread
    auto load_chunk = [&](int s, int ck) {
        const int kb = g0 + ck * KCHUNK;
        const uint32_t st = sb + s * STAGE_BYTES;
        #pragma unroll
        for (int it = 0; it < 16; ++it) {
            int i = it * 256 + tid;            // 0..4095
            int r = (i >> 4) & 127, c = i & 15;
            if (i < 2048) {
                const void* src = (const void*)(d_A + (size_t)r * NMAX + kb + c * 8);
                CPASYNC16(st + swz(r, c), src);
            } else {
                const void* src = (const void*)(d_B + (size_t)(ntb + r) * NMAX + kb + c * 8);
                CPASYNC16(st + SM_B_OFF + swz(r, c), src);
            }
        }
        asm volatile("cp.async.commit_group;" ::: "memory");
    };

    load_chunk(0, 0);

    const int NCHUNK = KSLICE / KCHUNK;   // 4
    for (int ck = 0; ck < NCHUNK; ++ck) {
        if (ck + 1 < NCHUNK) load_chunk((ck + 1) & 1, ck + 1);
        if (ck + 1 < NCHUNK)
            asm volatile("cp.async.wait_group 1;" ::: "memory");
        else
            asm volatile("cp.async.wait_group 0;" ::: "memory");
        __syncthreads();

        const uint32_t st = sb + (ck & 1) * STAGE_BYTES;
        #pragma unroll
        for (int ks = 0; ks < 8; ++ks) {
            const int c0 = ks * 2;
            uint32_t a[2][4];
            #pragma unroll
            for (int mf = 0; mf < 2; ++mf)
                LDSM4(a[mf][0], a[mf][1], a[mf][2], a[mf][3],
                      st + swz(wm + mf * 16 + arow, c0 + acadd));
            uint32_t b[8][2];
            #pragma unroll
            for (int bq = 0; bq < 4; ++bq) {
                uint32_t r0, r1, r2, r3;
                LDSM4(r0, r1, r2, r3,
                      st + SM_B_OFF + swz(wn + bq * 16 + brow, c0 + bcadd));
                b[2 * bq][0] = r0; b[2 * bq][1] = r1;
                b[2 * bq + 1][0] = r2; b[2 * bq + 1][1] = r3;
            }
            #pragma unroll
            for (int mf = 0; mf < 2; ++mf)
                #pragma unroll
                for (int nf = 0; nf < 8; ++nf)
                    MMA16816(acc[mf][nf], a[mf], b[nf]);
        }
        __syncthreads();
    }

    // ---- store 128x128 fp32 partial for this split
    float* part = &d_Part[blockIdx.y][0][0];
    #pragma unroll
    for (int mf = 0; mf < 2; ++mf) {
        #pragma unroll
        for (int nf = 0; nf < 8; ++nf) {
            int row = wm + mf * 16 + (lane >> 2);
            int cc  = ntb + wn + nf * 8 + (lane & 3) * 2;
            float2 v0 = make_float2(acc[mf][nf][0], acc[mf][nf][1]);
            float2 v1 = make_float2(acc[mf][nf][2], acc[mf][nf][3]);
            *reinterpret_cast<float2*>(part + (size_t)row * 512 + cc)       = v0;
            *reinterpret_cast<float2*>(part + (size_t)(row + 8) * 512 + cc) = v1;
        }
    }
}

// ---------------- finalize: reduce splits, divide, tile-scatter --------------
__global__ void __launch_bounds__(256) finalize_kernel(
    float* __restrict__ out, const int* __restrict__ tileHW,
    const int* __restrict__ chunkG, int N)
{
    int p = blockIdx.x * blockDim.x + threadIdx.x;
    if (p >= HH * WW) return;
    int y = p >> 7, x = p & 127;

    float r = 0.f, g = 0.f, b = 0.f, d = 0.f;
    #pragma unroll
    for (int s = 0; s < NSPLIT; ++s) {
        r += d_Part[s][y][x];
        g += d_Part[s][y][128 + x];
        b += d_Part[s][y][256 + x];
        d += d_Part[s][y][384 + x];
    }

    int cg = chunkG[0];
    if (cg <= 0 || cg > N) cg = N;
    d += (float)(N / cg) * EPSc;

    int tw = tileHW[0];
    if (tw <= 0 || tw > 128) tw = 64;
    int step = tw * tw;
    int t = p / step;
    int q = p - t * step;

    float inv = __fdividef(1.f, d);
    float* o = out + (size_t)t * 3 * step + q;
    o[0]        = r * inv;
    o[step]     = g * inv;
    o[2 * step] = b * inv;
}

// ---------------- launch -----------------------------------------------------
extern "C" void kernel_launch(void* const* d_in, const int* in_sizes, int n_in,
                              void* d_out, int out_size)
{
    const float* pos = (const float*)d_in[0];
    const float* col = (const float*)d_in[1];
    const float* opa = (const float*)d_in[2];
    const float* sca = (const float*)d_in[3];
    const float* qv  = (const float*)d_in[4];
    const float* tv  = (const float*)d_in[5];
    const int*   tHW = (n_in > 6) ? (const int*)d_in[6] : nullptr;
    const int*   cG  = (n_in > 7) ? (const int*)d_in[7] : nullptr;

    int N = in_sizes[0] / 3;
    if (N > NMAX) N = NMAX;

    prep_kernel<<<NMAX / 128, 1024>>>(pos, col, opa, sca, qv, tv);

    cudaFuncSetAttribute(gemm_kernel, cudaFuncAttributeMaxDynamicSharedMemorySize, SMEM_TOTAL);
    gemm_kernel<<<dim3(4, NSPLIT), 256, SMEM_TOTAL>>>();

    finalize_kernel<<<(HH * WW + 255) / 256, 256>>>((float*)d_out, tHW, cG, N);
}